// round 16
// baseline (speedup 1.0000x reference)
#include <cuda_runtime.h>
#include <cuda_bf16.h>

// GraphAddPooling: out[g] = sum_{i: batch[i]==g} x[i]
// x: [200000, 256] fp32, batch: sorted (int32/int64, detected), out: [512,256] fp32.
//
// R9 engine (reproduced 6x: 35.5-36.3us kernel, 73-75% DRAM) + ONE addition:
// while warps 0-1 run the seeded bound search (a ~0.5us chip-wide DRAM-idle
// bubble at T=0, since all 1024 blocks search simultaneously), warps 2-7
// issue prefetch.global.L2 for the 48 rows at the EXPECTED segment start
// (E = g*n/nseg, this block's column half: 192 threads x one 128B line).
// Fire-and-forget, no registers, no correctness dependence; rows near E are
// read by this or a neighboring block within microseconds, so the priming is
// traffic-neutral and converts start-of-stream DRAM misses into L2 hits.
//
// Everything else identical: 1024 blocks (segment x column-half) x 256 thr,
// stride-8 interleave, depth-4 predicated prefetch, smem combine, plain
// disjoint stores. No atomics, no zeroing, no cross-block sync, one launch.

#define NCOLS   256
#define VCOLS   64      // float4 per full row
#define LANES   32      // float4 lanes per column half (128 cols = 512B)
#define STREAMS 8
#define TPB     256
#define SEED_M  1500    // half-window for seeded search (6.7 sigma)
#define PFROWS  48      // speculative L2-prime rows per block

// Plain k-ary lower_bound rounds on [lo, lo+rem).
__device__ __forceinline__ long klb_rounds(const int* __restrict__ b, int shift,
                                           long lo, long rem, int target, int lane) {
    while (rem > 0) {
        long chunk = (rem + 32) / 33;
        long p = lo + chunk * (lane + 1) - 1;
        bool lt = false;
        if (p < lo + rem) lt = (b[p << shift] < target);
        unsigned m = __ballot_sync(0xffffffffu, lt);
        int k = __popc(m);
        lo += (long)k * chunk;
        long r2 = rem - (long)k * chunk;
        rem = (r2 <= 0) ? 0 : ((r2 >= chunk) ? (chunk - 1) : r2);
    }
    return lo;
}

// Seeded lower_bound: round-1 partition probes + window-validity probes are
// independent loads issued together (one memory round), then 2 more rounds.
__device__ __forceinline__ int seeded_lower_bound(const int* __restrict__ b,
                                                  int shift, int n, int nseg,
                                                  int target, int lane) {
    long E = (long)target * n / nseg;
    long lo0 = E - SEED_M; if (lo0 < 0) lo0 = 0;
    long hi0 = E + SEED_M; if (hi0 > n) hi0 = n;
    long rem0 = hi0 - lo0;

    long chunk = (rem0 + 32) / 33;
    long p = lo0 + chunk * (lane + 1) - 1;
    bool lt = false;
    if (p < hi0) lt = (b[p << shift] < target);
    // validity probes (independent of partition probes; broadcast loads)
    bool vlo = (lo0 == 0) || (b[(lo0 - 1) << shift] < target);
    bool vhi = (hi0 == n) || (b[(hi0 - 1) << shift] >= target);
    unsigned m = __ballot_sync(0xffffffffu, lt);

    if (vlo && vhi) {
        int k = __popc(m);
        long lo = lo0 + (long)k * chunk;
        long r2 = rem0 - (long)k * chunk;
        long rem = (r2 <= 0) ? 0 : ((r2 >= chunk) ? (chunk - 1) : r2);
        return (int)klb_rounds(b, shift, lo, rem, target, lane);
    }
    // window missed (never for this data; guaranteed-correct fallback)
    return (int)klb_rounds(b, shift, 0, n, target, lane);
}

__global__ __launch_bounds__(TPB, 7) void gap_seg_kernel(
    const float4* __restrict__ x,
    const int* __restrict__ b32,     // batch viewed as int32 words
    float4* __restrict__ out,
    int nrows, int nseg)
{
    __shared__ int    s_bounds[2];
    __shared__ float4 s_part[STREAMS][LANES];

    const int g    = blockIdx.x >> 1;        // segment
    const int ch   = blockIdx.x & 1;         // column half
    const int tid  = threadIdx.x;
    const int lane = tid & (LANES - 1);      // float4 lane within half
    const int ys   = tid >> 5;               // row stream 0..7 (== warp id)

    // int64 vs int32 batch: sorted ids < nseg, so little-endian int64 puts a
    // zero high word at int32 index nrows-1.
    const int shift = (b32[nrows - 1] == 0) ? 1 : 0;

    if (ys < 2) {
        int r = seeded_lower_bound(b32, shift, nrows, nseg, g + ys, lane);
        if (lane == 0) s_bounds[ys] = r;
    } else {
        // Warps 2-7: speculative L2 prime of rows [E, E+PFROWS) in this
        // block's column half, overlapping the search's dependent probes.
        // 192 threads x one 128B line = 48 rows x 512B.
        long E = (long)g * nrows / nseg;
        int t  = (ys - 2) * 32 + lane;       // 0..191
        long pr = E + (t >> 2);              // row
        if (pr < nrows) {
            const char* pp = (const char*)(x + pr * VCOLS + ch * LANES)
                             + (t & 3) * 128;
            asm volatile("prefetch.global.L2 [%0];" :: "l"(pp));
        }
    }
    __syncthreads();
    const int lo = s_bounds[0];
    const int hi = s_bounds[1];

    const float4* xq = x + (size_t)ch * LANES + lane;   // column offset

    // Depth-4 pipelined stream over rows lo+ys, lo+ys+8, ...
    float4 acc = make_float4(0.f, 0.f, 0.f, 0.f);
    int r = lo + ys;

    float4 va = make_float4(0.f, 0.f, 0.f, 0.f);
    float4 vb = make_float4(0.f, 0.f, 0.f, 0.f);
    float4 vc = make_float4(0.f, 0.f, 0.f, 0.f);
    if (r < hi)                va = xq[(size_t)r * VCOLS];
    if (r + STREAMS < hi)      vb = xq[(size_t)(r + STREAMS) * VCOLS];
    if (r + 2 * STREAMS < hi)  vc = xq[(size_t)(r + 2 * STREAMS) * VCOLS];

    for (; r < hi; r += STREAMS) {
        float4 vd = make_float4(0.f, 0.f, 0.f, 0.f);
        if (r + 3 * STREAMS < hi) vd = xq[(size_t)(r + 3 * STREAMS) * VCOLS];
        acc.x += va.x; acc.y += va.y; acc.z += va.z; acc.w += va.w;
        va = vb; vb = vc; vc = vd;
    }

    s_part[ys][lane] = acc;
    __syncthreads();

    if (tid < LANES) {
        float4 a = s_part[0][tid];
        #pragma unroll
        for (int s = 1; s < STREAMS; s++) {
            float4 b = s_part[s][tid];
            a.x += b.x; a.y += b.y; a.z += b.z; a.w += b.w;
        }
        // Disjoint (segment, half) output -> unconditional plain store
        // (also initializes empty segments over the poisoned buffer).
        out[(size_t)g * VCOLS + ch * LANES + tid] = a;
    }
}

extern "C" void kernel_launch(void* const* d_in, const int* in_sizes, int n_in,
                              void* d_out, int out_size) {
    const float4* x  = (const float4*)d_in[0];
    const int* batch = (const int*)d_in[1];
    float4* out      = (float4*)d_out;

    const int nrows = in_sizes[1];        // 200000
    const int nseg  = out_size / NCOLS;   // 512

    gap_seg_kernel<<<nseg * 2, TPB>>>(x, batch, out, nrows, nseg);
}

// round 17
// speedup vs baseline: 1.0164x; 1.0164x over previous
#include <cuda_runtime.h>
#include <cuda_bf16.h>

// GraphAddPooling: out[g] = sum_{i: batch[i]==g} x[i]
// x: [200000, 256] fp32, batch: sorted (int32/int64, detected), out: [512,256] fp32.
//
// FINAL. R6/R9 engine, reproduced 6x: 35.5-36.3us kernel, 73-75% DRAM
// (5.8-5.9 TB/s ~ 86% of the B300 path-independent LTS streaming cap),
// best total 36.96us, rel_err 3.8e-7.
//
// Single kernel, no atomics, no zeroing, no cross-block sync.
// One block per (segment, column half): 1024 blocks x 256 threads.
//   - seeded warp k-ary lower_bound: window E +/- 1500 (validity probes issued
//     concurrently with round-1 partition probes; guaranteed-correct
//     full-search fallback) -> 3 dependent probe rounds, mostly L2-warm
//   - 8 row-streams x 32 float4-lanes (512B per warp, coalesced), stride-8
//     interleave (beats warp-contiguous chunks 73.6 vs 71.8% DRAM), depth-4
//     predicated prefetch, plain loads
//   - smem combine, unconditional plain store (covers empty segments over
//     the poisoned output buffer)
//
// Ruled out by measurement (15 variations): in-kernel sync fusion
// (-4..-12us), warp-autonomous restructuring (-0.4us), hand-unrolled steady
// loops (-6us), depth-5 (+-0), warp-contiguous rows (-0.7us), speculative L2
// priming (+12MB traffic, -1us), __ldcs, column-quarter grids, per-row
// atomics; occupancy 42-94% had zero throughput effect (memory-system bound).

#define NCOLS   256
#define VCOLS   64      // float4 per full row
#define LANES   32      // float4 lanes per column half (128 cols = 512B)
#define STREAMS 8
#define TPB     256
#define SEED_M  1500    // half-window for seeded search (6.7 sigma)

// Plain k-ary lower_bound rounds on [lo, lo+rem).
__device__ __forceinline__ long klb_rounds(const int* __restrict__ b, int shift,
                                           long lo, long rem, int target, int lane) {
    while (rem > 0) {
        long chunk = (rem + 32) / 33;
        long p = lo + chunk * (lane + 1) - 1;
        bool lt = false;
        if (p < lo + rem) lt = (b[p << shift] < target);
        unsigned m = __ballot_sync(0xffffffffu, lt);
        int k = __popc(m);
        lo += (long)k * chunk;
        long r2 = rem - (long)k * chunk;
        rem = (r2 <= 0) ? 0 : ((r2 >= chunk) ? (chunk - 1) : r2);
    }
    return lo;
}

// Seeded lower_bound: round-1 partition probes + window-validity probes are
// independent loads issued together (one memory round), then 2 more rounds.
__device__ __forceinline__ int seeded_lower_bound(const int* __restrict__ b,
                                                  int shift, int n, int nseg,
                                                  int target, int lane) {
    long E = (long)target * n / nseg;
    long lo0 = E - SEED_M; if (lo0 < 0) lo0 = 0;
    long hi0 = E + SEED_M; if (hi0 > n) hi0 = n;
    long rem0 = hi0 - lo0;

    long chunk = (rem0 + 32) / 33;
    long p = lo0 + chunk * (lane + 1) - 1;
    bool lt = false;
    if (p < hi0) lt = (b[p << shift] < target);
    // validity probes (independent of partition probes; broadcast loads)
    bool vlo = (lo0 == 0) || (b[(lo0 - 1) << shift] < target);
    bool vhi = (hi0 == n) || (b[(hi0 - 1) << shift] >= target);
    unsigned m = __ballot_sync(0xffffffffu, lt);

    if (vlo && vhi) {
        int k = __popc(m);
        long lo = lo0 + (long)k * chunk;
        long r2 = rem0 - (long)k * chunk;
        long rem = (r2 <= 0) ? 0 : ((r2 >= chunk) ? (chunk - 1) : r2);
        return (int)klb_rounds(b, shift, lo, rem, target, lane);
    }
    // window missed (never for this data; guaranteed-correct fallback)
    return (int)klb_rounds(b, shift, 0, n, target, lane);
}

__global__ __launch_bounds__(TPB, 7) void gap_seg_kernel(
    const float4* __restrict__ x,
    const int* __restrict__ b32,     // batch viewed as int32 words
    float4* __restrict__ out,
    int nrows, int nseg)
{
    __shared__ int    s_bounds[2];
    __shared__ float4 s_part[STREAMS][LANES];

    const int g    = blockIdx.x >> 1;        // segment
    const int ch   = blockIdx.x & 1;         // column half
    const int tid  = threadIdx.x;
    const int lane = tid & (LANES - 1);      // float4 lane within half
    const int ys   = tid >> 5;               // row stream 0..7 (== warp id)

    // int64 vs int32 batch: sorted ids < nseg, so little-endian int64 puts a
    // zero high word at int32 index nrows-1.
    const int shift = (b32[nrows - 1] == 0) ? 1 : 0;

    if (ys < 2) {
        int r = seeded_lower_bound(b32, shift, nrows, nseg, g + ys, lane);
        if (lane == 0) s_bounds[ys] = r;
    }
    __syncthreads();
    const int lo = s_bounds[0];
    const int hi = s_bounds[1];

    const float4* xq = x + (size_t)ch * LANES + lane;   // column offset

    // Depth-4 pipelined stream over rows lo+ys, lo+ys+8, ...
    float4 acc = make_float4(0.f, 0.f, 0.f, 0.f);
    int r = lo + ys;

    float4 va = make_float4(0.f, 0.f, 0.f, 0.f);
    float4 vb = make_float4(0.f, 0.f, 0.f, 0.f);
    float4 vc = make_float4(0.f, 0.f, 0.f, 0.f);
    if (r < hi)                va = xq[(size_t)r * VCOLS];
    if (r + STREAMS < hi)      vb = xq[(size_t)(r + STREAMS) * VCOLS];
    if (r + 2 * STREAMS < hi)  vc = xq[(size_t)(r + 2 * STREAMS) * VCOLS];

    for (; r < hi; r += STREAMS) {
        float4 vd = make_float4(0.f, 0.f, 0.f, 0.f);
        if (r + 3 * STREAMS < hi) vd = xq[(size_t)(r + 3 * STREAMS) * VCOLS];
        acc.x += va.x; acc.y += va.y; acc.z += va.z; acc.w += va.w;
        va = vb; vb = vc; vc = vd;
    }

    s_part[ys][lane] = acc;
    __syncthreads();

    if (tid < LANES) {
        float4 a = s_part[0][tid];
        #pragma unroll
        for (int s = 1; s < STREAMS; s++) {
            float4 b = s_part[s][tid];
            a.x += b.x; a.y += b.y; a.z += b.z; a.w += b.w;
        }
        // Disjoint (segment, half) output -> unconditional plain store
        // (also initializes empty segments over the poisoned buffer).
        out[(size_t)g * VCOLS + ch * LANES + tid] = a;
    }
}

extern "C" void kernel_launch(void* const* d_in, const int* in_sizes, int n_in,
                              void* d_out, int out_size) {
    const float4* x  = (const float4*)d_in[0];
    const int* batch = (const int*)d_in[1];
    float4* out      = (float4*)d_out;

    const int nrows = in_sizes[1];        // 200000
    const int nseg  = out_size / NCOLS;   // 512

    gap_seg_kernel<<<nseg * 2, TPB>>>(x, batch, out, nrows, nseg);
}